// round 6
// baseline (speedup 1.0000x reference)
#include <cuda_runtime.h>
#include <cuda_bf16.h>
#include <math.h>
#include <cstdint>

// Problem dims
#define TGT   64
#define SRC   64
#define BATCH 32
#define HID   512
#define ATT   512

// Scratch (no cudaMalloc allowed)
__device__ float g_hpart[TGT * BATCH * ATT];   // [t*BATCH+b][a]
__device__ float g_spart[SRC * BATCH * ATT];   // [s*BATCH+b][a]
__device__ float g_scores[TGT * BATCH * SRC];  // [(t*BATCH+b)*SRC + s]
__device__ float g_WT[2 * HID * ATT];          // W transposed (tf32-rounded): [z][n][k]

// ---------------------------------------------------------------------------
// helpers
// ---------------------------------------------------------------------------
__device__ __forceinline__ float to_tf32(float x) {
    uint32_t u;
    asm("cvt.rna.tf32.f32 %0, %1;" : "=r"(u) : "f"(x));
    return __uint_as_float(u);
}

__device__ __forceinline__ float tanh_fast(float x) {
    float y;
    asm("tanh.approx.f32 %0, %1;" : "=f"(y) : "f"(x));
    return y;
}

__device__ __forceinline__ void mma_tf32(float* c, const float* a, const float* b) {
    uint32_t a0 = __float_as_uint(a[0]), a1 = __float_as_uint(a[1]);
    uint32_t a2 = __float_as_uint(a[2]), a3 = __float_as_uint(a[3]);
    uint32_t b0 = __float_as_uint(b[0]), b1 = __float_as_uint(b[1]);
    asm volatile(
        "mma.sync.aligned.m16n8k8.row.col.f32.tf32.tf32.f32 "
        "{%0,%1,%2,%3}, {%4,%5,%6,%7}, {%8,%9}, {%0,%1,%2,%3};"
        : "+f"(c[0]), "+f"(c[1]), "+f"(c[2]), "+f"(c[3])
        : "r"(a0), "r"(a1), "r"(a2), "r"(a3), "r"(b0), "r"(b1));
}

// ---------------------------------------------------------------------------
// Kernel 0: transpose W halves + tf32 rounding: g_WT[z][n][k] = tf32(Wa[z*512+k][n])
// ---------------------------------------------------------------------------
__global__ __launch_bounds__(256) void transpose_w(const float* __restrict__ Wa)
{
    __shared__ float t[32][33];
    const int tx = threadIdx.x, ty = threadIdx.y;
    const int k0 = blockIdx.x * 32, n0 = blockIdx.y * 32, z = blockIdx.z;
#pragma unroll
    for (int r = 0; r < 32; r += 8)
        t[ty + r][tx] = Wa[(z * HID + k0 + ty + r) * ATT + n0 + tx];
    __syncthreads();
#pragma unroll
    for (int r = 0; r < 32; r += 8)
        g_WT[z * HID * ATT + (n0 + ty + r) * HID + k0 + tx] = to_tf32(t[tx][ty + r]);
}

// ---------------------------------------------------------------------------
// Kernel 1: tf32 mma.sync GEMM.  C[m][n] = sum_k A[m][k] * WT[n][k]
// 128x128 CTA tile, KT=32 double-buffered, one sync per stage. (unchanged)
// ---------------------------------------------------------------------------
#define KT    32
#define RSTR  36
#define TILEF (128 * RSTR)

__global__ __launch_bounds__(256) void gemm_mma(
    const float* __restrict__ h_t,
    const float* __restrict__ src)
{
    extern __shared__ __align__(16) float sm[];
    float* const Abuf[2] = { sm,         sm + 2 * TILEF };
    float* const Bbuf[2] = { sm + TILEF, sm + 3 * TILEF };

    const int tid  = threadIdx.x;
    const int lane = tid & 31;
    const int wid  = tid >> 5;
    const int g    = lane >> 2;
    const int tg   = lane & 3;

    const int wm = (wid >> 1) * 32;
    const int wn = (wid & 1) * 64;

    const int ntile = blockIdx.x;
    const int mtile = blockIdx.y;
    const int z  = mtile >> 4;
    const float* A = (z == 0) ? h_t : src;
    const float* B = g_WT + z * HID * ATT;
    float*       C = (z == 0) ? g_hpart : g_spart;
    const int m0 = (mtile & 15) * 128;
    const int n0 = ntile * 128;

    float acc[2][8][4];
#pragma unroll
    for (int mi = 0; mi < 2; mi++)
#pragma unroll
        for (int ni = 0; ni < 8; ni++)
#pragma unroll
            for (int j = 0; j < 4; j++) acc[mi][ni][j] = 0.f;

#pragma unroll
    for (int r = 0; r < 4; r++) {
        const int idx = r * 256 + tid;
        const int row = idx >> 3;
        const int c4  = idx & 7;
        float4 av = *(const float4*)(A + (m0 + row) * HID + c4 * 4);
        float4 bv = *(const float4*)(B + (n0 + row) * HID + c4 * 4);
        float* da = Abuf[0] + row * RSTR + c4 * 4;
        float* db = Bbuf[0] + row * RSTR + c4 * 4;
        *(float4*)da = make_float4(to_tf32(av.x), to_tf32(av.y), to_tf32(av.z), to_tf32(av.w));
        *(float4*)db = bv;   // already tf32-rounded
    }
    __syncthreads();

    for (int s = 0; s < 16; s++) {
        const int cur = s & 1;
        float4 ra[4], rb[4];
        if (s < 15) {
            const int kt = (s + 1) * KT;
#pragma unroll
            for (int r = 0; r < 4; r++) {
                const int idx = r * 256 + tid;
                const int row = idx >> 3;
                const int c4  = idx & 7;
                ra[r] = *(const float4*)(A + (m0 + row) * HID + kt + c4 * 4);
                rb[r] = *(const float4*)(B + (n0 + row) * HID + kt + c4 * 4);
            }
        }

        const float* Ab = Abuf[cur];
        const float* Bb = Bbuf[cur];
#pragma unroll
        for (int ks = 0; ks < 4; ks++) {
            const int k0 = ks * 8;
            float a[2][4];
#pragma unroll
            for (int mi = 0; mi < 2; mi++) {
                const float* ap = Ab + (wm + mi * 16 + g) * RSTR + k0 + tg;
                a[mi][0] = ap[0];
                a[mi][1] = ap[8 * RSTR];
                a[mi][2] = ap[4];
                a[mi][3] = ap[8 * RSTR + 4];
            }
            float b[8][2];
#pragma unroll
            for (int ni = 0; ni < 8; ni++) {
                const float* bp = Bb + (wn + ni * 8 + g) * RSTR + k0 + tg;
                b[ni][0] = bp[0];
                b[ni][1] = bp[4];
            }
#pragma unroll
            for (int mi = 0; mi < 2; mi++)
#pragma unroll
                for (int ni = 0; ni < 8; ni++)
                    mma_tf32(acc[mi][ni], a[mi], b[ni]);
        }

        if (s < 15) {
            const int nxt = cur ^ 1;
#pragma unroll
            for (int r = 0; r < 4; r++) {
                const int idx = r * 256 + tid;
                const int row = idx >> 3;
                const int c4  = idx & 7;
                float* da = Abuf[nxt] + row * RSTR + c4 * 4;
                float* db = Bbuf[nxt] + row * RSTR + c4 * 4;
                *(float4*)da = make_float4(to_tf32(ra[r].x), to_tf32(ra[r].y),
                                           to_tf32(ra[r].z), to_tf32(ra[r].w));
                *(float4*)db = rb[r];
            }
            __syncthreads();
        }
    }

#pragma unroll
    for (int mi = 0; mi < 2; mi++) {
#pragma unroll
        for (int ni = 0; ni < 8; ni++) {
            const int row = m0 + wm + mi * 16 + g;
            const int col = n0 + wn + ni * 8 + 2 * tg;
            *(float2*)(C + row * ATT + col)       = make_float2(acc[mi][ni][0], acc[mi][ni][1]);
            *(float2*)(C + (row + 8) * ATT + col) = make_float2(acc[mi][ni][2], acc[mi][ni][3]);
        }
    }
}

// ---------------------------------------------------------------------------
// Kernel 2: scores[s,t,b] = sum_a tanh(h_part[t,b,a] + s_part[s,b,a]) * Va[a]
// (unchanged — at MUFU.TANH floor)
// ---------------------------------------------------------------------------
#define SSTR 516

__global__ __launch_bounds__(256) void scores_kernel(
    const float* __restrict__ Va)
{
    extern __shared__ float smem[];
    float* hs = smem;                 // 16 * SSTR
    float* ss = smem + 16 * SSTR;     // 16 * SSTR
    float* va = smem + 32 * SSTR;     // 512

    const int b     = blockIdx.z;
    const int t0    = blockIdx.y * 16;
    const int sbase = blockIdx.x * 32;
    const int tid   = threadIdx.x;

    va[tid]       = Va[tid];
    va[tid + 256] = Va[tid + 256];

#pragma unroll
    for (int r = 0; r < 8; r++) {
        int idx  = r * 256 + tid;
        int row  = idx >> 7;
        int col4 = idx & 127;
        float4 v = *(const float4*)(g_hpart + ((t0 + row) * BATCH + b) * ATT + col4 * 4);
        *(float4*)(hs + row * SSTR + col4 * 4) = v;
    }

    const int si = tid & 15;
    const int ti = tid >> 4;

    for (int sc = 0; sc < 32; sc += 16) {
        __syncthreads();
#pragma unroll
        for (int r = 0; r < 8; r++) {
            int idx  = r * 256 + tid;
            int row  = idx >> 7;
            int col4 = idx & 127;
            float4 v = *(const float4*)(g_spart + ((sbase + sc + row) * BATCH + b) * ATT + col4 * 4);
            *(float4*)(ss + row * SSTR + col4 * 4) = v;
        }
        __syncthreads();

        const float* hp = hs + ti * SSTR;
        const float* sp = ss + si * SSTR;
        float acc = 0.f;
#pragma unroll 4
        for (int a = 0; a < 512; a += 4) {
            float4 h4 = *(const float4*)(hp + a);
            float4 s4 = *(const float4*)(sp + a);
            float4 v4 = *(const float4*)(va + a);
            acc = fmaf(tanh_fast(h4.x + s4.x), v4.x, acc);
            acc = fmaf(tanh_fast(h4.y + s4.y), v4.y, acc);
            acc = fmaf(tanh_fast(h4.z + s4.z), v4.z, acc);
            acc = fmaf(tanh_fast(h4.w + s4.w), v4.w, acc);
        }
        const int s = sbase + sc + si;
        const int t = t0 + ti;
        g_scores[(t * BATCH + b) * SRC + s] = acc;
    }
}

// ---------------------------------------------------------------------------
// Kernel 3: fused softmax + tensor-core context.
// Per block: one b, one 128-wide h-chunk. attn = softmax(scores[:,:,b]) done
// in-block; context[t, b, h] = sum_s attn[s,t] * src[s,b,h] via tf32 mma
// (M=64 t, N=128 h, K=64 s). Grid = (4 hc, 32 b) = 128 blocks = 1 wave.
// ---------------------------------------------------------------------------
#define ASTR 68    // attn^T smem stride [t][s]
#define CSTR 132   // src chunk smem stride [s][h']

__global__ __launch_bounds__(256) void softmax_context_kernel(
    const float* __restrict__ src,
    float* __restrict__ out)
{
    extern __shared__ float dsm[];
    float* at = dsm;                 // attn^T [t][s]: 64*ASTR = 4352 floats
    float* ss = dsm + 64 * ASTR;     // src chunk [s][h']: 64*CSTR = 8448 floats

    const int b   = blockIdx.y;
    const int hc  = blockIdx.x;      // h-chunk 0..3
    const int h0  = hc * 128;
    const int tid = threadIdx.x;
    const int wid  = tid >> 5;
    const int lane = tid & 31;

    // --- softmax: warp wi handles t = wi*8 .. wi*8+7, writes attn^T tf32 ---
#pragma unroll
    for (int r = 0; r < 8; r++) {
        const int t = wid * 8 + r;
        const float* srow = g_scores + (t * BATCH + b) * SRC;
        float v0 = srow[lane];
        float v1 = srow[lane + 32];
        float mx = fmaxf(v0, v1);
#pragma unroll
        for (int o = 16; o > 0; o >>= 1)
            mx = fmaxf(mx, __shfl_xor_sync(0xffffffffu, mx, o));
        float e0 = __expf(v0 - mx);
        float e1 = __expf(v1 - mx);
        float sum = e0 + e1;
#pragma unroll
        for (int o = 16; o > 0; o >>= 1)
            sum += __shfl_xor_sync(0xffffffffu, sum, o);
        float inv = 1.0f / sum;
        at[t * ASTR + lane]      = to_tf32(e0 * inv);
        at[t * ASTR + lane + 32] = to_tf32(e1 * inv);
    }

    // --- stage src chunk: 64 rows x 128 floats (32 float4/row), tf32-rounded ---
#pragma unroll
    for (int r = 0; r < 8; r++) {
        const int idx = r * 256 + tid;     // 0..2047 float4 slots
        const int s   = idx >> 5;
        const int c4  = idx & 31;
        float4 v = *(const float4*)(src + (s * BATCH + b) * HID + h0 + c4 * 4);
        *(float4*)(ss + s * CSTR + c4 * 4) =
            make_float4(to_tf32(v.x), to_tf32(v.y), to_tf32(v.z), to_tf32(v.w));
    }
    __syncthreads();

    // --- mma: warp tile 16(t) x 64(h'), warps 4x2 ---
    const int g  = lane >> 2;
    const int tg = lane & 3;
    const int wm = (wid & 3) * 16;       // t offset
    const int wn = (wid >> 2) * 64;      // h' offset

    float acc[8][4];
#pragma unroll
    for (int ni = 0; ni < 8; ni++)
#pragma unroll
        for (int j = 0; j < 4; j++) acc[ni][j] = 0.f;

#pragma unroll
    for (int ks = 0; ks < 8; ks++) {
        const int k0 = ks * 8;
        float a[4];
        {
            const float* ap = at + (wm + g) * ASTR + k0 + tg;
            a[0] = ap[0];
            a[1] = ap[8 * ASTR];
            a[2] = ap[4];
            a[3] = ap[8 * ASTR + 4];
        }
        float bfr[8][2];
#pragma unroll
        for (int ni = 0; ni < 8; ni++) {
            const float* bp = ss + (k0 + tg) * CSTR + wn + ni * 8 + g;
            bfr[ni][0] = bp[0];
            bfr[ni][1] = bp[4 * CSTR];
        }
#pragma unroll
        for (int ni = 0; ni < 8; ni++)
            mma_tf32(acc[ni], a, bfr[ni]);
    }

    // --- writeback: C[t][h'] -> out[(t*BATCH+b)*HID + h0 + h'] ---
#pragma unroll
    for (int ni = 0; ni < 8; ni++) {
        const int t   = wm + g;
        const int col = h0 + wn + ni * 8 + 2 * tg;
        *(float2*)(out + (t * BATCH + b) * HID + col)       = make_float2(acc[ni][0], acc[ni][1]);
        *(float2*)(out + ((t + 8) * BATCH + b) * HID + col) = make_float2(acc[ni][2], acc[ni][3]);
    }
}

// ---------------------------------------------------------------------------
extern "C" void kernel_launch(void* const* d_in, const int* in_sizes, int n_in,
                              void* d_out, int out_size)
{
    const float* h_t  = (const float*)d_in[0];   // (64, 32, 512)
    const float* srce = (const float*)d_in[1];   // (64, 32, 512)
    const float* Wa   = (const float*)d_in[2];   // (1024, 512)
    const float* Va   = (const float*)d_in[3];   // (512,)
    float* out = (float*)d_out;                  // (64, 32, 512)

    (void)in_sizes; (void)n_in; (void)out_size;

    // 0) transpose + tf32-round W halves into g_WT
    transpose_w<<<dim3(16, 16, 2), dim3(32, 8)>>>(Wa);

    // 1) tf32 mma GEMMs: grid (n tiles = 4, m tiles = 32) = 128 CTAs
    const int gemm_smem = 4 * TILEF * (int)sizeof(float);   // 73728 B
    cudaFuncSetAttribute(gemm_mma,
                         cudaFuncAttributeMaxDynamicSharedMemorySize, gemm_smem);
    gemm_mma<<<dim3(4, 32), 256, gemm_smem>>>(h_t, srce);

    // 2) scores: grid (s-halves=2, t-tiles=4, b=32)
    const int smem_bytes = (32 * SSTR + 512) * sizeof(float);
    cudaFuncSetAttribute(scores_kernel,
                         cudaFuncAttributeMaxDynamicSharedMemorySize, smem_bytes);
    scores_kernel<<<dim3(2, 4, 32), 256, smem_bytes>>>(Va);

    // 3) fused softmax + mma context: grid (hc=4, b=32) = 128 blocks
    const int smc_smem = (64 * ASTR + 64 * CSTR) * (int)sizeof(float);  // 51200 B
    cudaFuncSetAttribute(softmax_context_kernel,
                         cudaFuncAttributeMaxDynamicSharedMemorySize, smc_smem);
    softmax_context_kernel<<<dim3(4, 32), 256, smc_smem>>>(srce, out);
}